// round 6
// baseline (speedup 1.0000x reference)
#include <cuda_runtime.h>
#include <math.h>

#define N       4096
#define NFEAT   512
#define NHID    64
#define NHEADS  8
#define NCLASS  16
#define HD      512   /* NHEADS*NHID */

// ---------------- scratch (device globals; no allocations) ----------------
__device__ unsigned g_adj[N * 128];            // bit j of row i -> g_adj[i*128 + (j>>5)] >> (j&31)
__device__ float g_W1r[NFEAT * HD];            // [f][h*64+k]
__device__ float g_Wh1[N * HD];                // [i][h*64+k]
__device__ float g_fs1[N * NHEADS];            // raw src logit
__device__ float g_fd1[N * NHEADS];            // raw dst logit
__device__ float g_ed1[N * NHEADS];            // exp(fd)
__device__ float g_ed1b[N * NHEADS];           // exp(0.2*fd)
__device__ float g_hcat[N * HD];               // layer-1 output (post ELU)
__device__ float g_Wh2[N * NCLASS];
__device__ float g_fs2[N], g_fd2[N], g_ed2[N], g_ed2b[N];

// ---------------- K0: pack adjacency into bitmask ----------------
__global__ void k_pack(const int* __restrict__ adj) {
    int i = blockIdx.x;
    int t = threadIdx.x;                       // 1024 threads
    for (int base = 0; base < N; base += 1024) {
        int j = base + t;
        int v = adj[(size_t)i * N + j];
        unsigned m = __ballot_sync(0xffffffffu, v > 0);
        if ((t & 31) == 0) g_adj[i * 128 + (j >> 5)] = m;
    }
}

// ---------------- K0b: rearrange W1[h][f][k] -> W1r[f][h*64+k] ----------------
__global__ void k_w1r(const float* __restrict__ W1) {
    int idx = blockIdx.x * 256 + threadIdx.x;  // 262144 total
    int k = idx & 63;
    int f = (idx >> 6) & 511;
    int h = idx >> 15;
    g_W1r[f * HD + h * 64 + k] = W1[idx];
}

// ---------------- K1: Wh1 = x @ W1r   (4096x512 @ 512x512), f32x2 FMAs ----------------
__global__ __launch_bounds__(256) void k_gemm1(const float* __restrict__ x) {
    __shared__ __align__(16) float As[16 * 68];   // [k][row], padded (68*4 = 272B, 16B aligned per k)
    __shared__ __align__(16) float Bs[16 * 64];   // [k][col]
    int m0 = blockIdx.x * 64, n0 = blockIdx.y * 64;
    int t = threadIdx.x;
    int tr = t >> 4, tc = t & 15;
    unsigned long long acc2[4][2] = {};
    for (int kk = 0; kk < NFEAT; kk += 16) {
        {   // load A tile 64 rows x 16 k
            int c = t & 15, r0 = t >> 4;
            #pragma unroll
            for (int rr = 0; rr < 4; rr++) {
                int r = r0 + rr * 16;
                As[c * 68 + r] = x[(size_t)(m0 + r) * NFEAT + kk + c];
            }
        }
        {   // load B tile 16 k x 64 n
            int n = t & 63, k0 = t >> 6;
            #pragma unroll
            for (int q = 0; q < 4; q++) {
                int k = k0 + q * 4;
                Bs[k * 64 + n] = g_W1r[(size_t)(kk + k) * HD + n0 + n];
            }
        }
        __syncthreads();
        #pragma unroll
        for (int k = 0; k < 16; k++) {
            float4 a4 = *(const float4*)&As[k * 68 + tr * 4];
            ulonglong2 b2 = *(const ulonglong2*)&Bs[k * 64 + tc * 4];
            float av[4] = {a4.x, a4.y, a4.z, a4.w};
            #pragma unroll
            for (int i = 0; i < 4; i++) {
                unsigned au = __float_as_uint(av[i]);
                unsigned long long ad;
                asm("mov.b64 %0, {%1, %1};" : "=l"(ad) : "r"(au));
                asm("fma.rn.f32x2 %0, %1, %2, %0;" : "+l"(acc2[i][0]) : "l"(b2.x), "l"(ad));
                asm("fma.rn.f32x2 %0, %1, %2, %0;" : "+l"(acc2[i][1]) : "l"(b2.y), "l"(ad));
            }
        }
        __syncthreads();
    }
    #pragma unroll
    for (int i = 0; i < 4; i++) {
        int row = m0 + tr * 4 + i;
        float4 v;
        v.x = __uint_as_float((unsigned)(acc2[i][0] & 0xffffffffull));
        v.y = __uint_as_float((unsigned)(acc2[i][0] >> 32));
        v.z = __uint_as_float((unsigned)(acc2[i][1] & 0xffffffffull));
        v.w = __uint_as_float((unsigned)(acc2[i][1] >> 32));
        *(float4*)&g_Wh1[(size_t)row * HD + n0 + tc * 4] = v;
    }
}

// ---------------- K1b: layer-1 attention logits + exp tables ----------------
__global__ void k_logit1(const float* __restrict__ a1) {
    int i = blockIdx.x;
    int w = threadIdx.x >> 5, l = threadIdx.x & 31;   // warp w = head w
    const float* wh = &g_Wh1[(size_t)i * HD + w * 64];
    const float* a  = &a1[w * 128];
    float s = wh[l] * a[l]      + wh[l + 32] * a[l + 32];
    float d = wh[l] * a[64 + l] + wh[l + 32] * a[96 + l];
    #pragma unroll
    for (int o = 16; o; o >>= 1) {
        s += __shfl_xor_sync(0xffffffffu, s, o);
        d += __shfl_xor_sync(0xffffffffu, d, o);
    }
    if (l == 0) {
        g_fs1[i * 8 + w]  = s;
        g_fd1[i * 8 + w]  = d;
        g_ed1[i * 8 + w]  = expf(d);
        g_ed1b[i * 8 + w] = expf(0.2f * d);
    }
}

// ---------------- K2: fused masked-softmax attention, layer 1 ----------------
// 32 rows per block; 512 threads; CJ=16 j-columns per chunk.
// Per chunk: (1) batch-prefetch 16 Wh values into regs (MLP=16, latency hidden
// under phase A + BAR), (2) phase A builds P tile [16 j][8 h][32 r] in SMEM,
// (3) phase B: thread t owns output column o=t, accumulates 32 rows as 16
// packed fp32x2 pairs. Epilogue: /Z then ELU.
#define RI 32
#define CJ 16
__global__ __launch_bounds__(512, 1) void k_att1(void) {
    __shared__ unsigned sAdj[RI][128];                 // 16 KB
    __shared__ __align__(16) float sP[CJ][NHEADS * RI]; // 16 KB  [jj][h*32 + r]
    __shared__ float sZ[RI][8];
    __shared__ float sFs[RI][8], sEi[RI][8], sEib[RI][8];

    int i0 = blockIdx.x * RI;
    int t = threadIdx.x;

    for (int idx = t; idx < RI * 128; idx += 512)
        sAdj[idx >> 7][idx & 127] = g_adj[(size_t)(i0 + (idx >> 7)) * 128 + (idx & 127)];
    if (t < RI * 8) {
        int r = t >> 3, h = t & 7;
        float fs = g_fs1[(i0 + r) * 8 + h];
        sFs[r][h] = fs;
        sEi[r][h] = expf(fs);
        sEib[r][h] = expf(0.2f * fs);
        sZ[r][h] = 0.f;
    }
    __syncthreads();

    int jj = t >> 5, r = t & 31;          // phase-A ids (16 x 32)
    int h  = t >> 6;                       // phase-B head; o = t

    // per-row constants for phase A in registers
    float myFs[8], myEi[8], myEib[8];
    #pragma unroll
    for (int hh = 0; hh < 8; hh++) {
        myFs[hh] = sFs[r][hh];
        myEi[hh] = sEi[r][hh];
        myEib[hh] = sEib[r][hh];
    }

    float zloc[8] = {};
    unsigned long long acc2[16] = {};     // 32 fp32 accumulators as 16 packed pairs

    for (int cbase = 0; cbase < N; cbase += CJ) {
        // ---- prefetch Wh column t for the 16 j-rows of this chunk ----
        float wh[CJ];
        #pragma unroll
        for (int q = 0; q < CJ; q++)
            wh[q] = __ldg(&g_Wh1[(size_t)(cbase + q) * HD + t]);

        // ---- phase A: build P tile ----
        {
            int j = cbase + jj;
            unsigned bit = (sAdj[r][j >> 5] >> (j & 31)) & 1u;
            const float4* fd4 = (const float4*)&g_fd1[j * 8];
            const float4* ed4 = (const float4*)&g_ed1[j * 8];
            const float4* eb4 = (const float4*)&g_ed1b[j * 8];
            float fd[8], ed[8], eb[8];
            float4 v;
            v = fd4[0]; fd[0]=v.x; fd[1]=v.y; fd[2]=v.z; fd[3]=v.w;
            v = fd4[1]; fd[4]=v.x; fd[5]=v.y; fd[6]=v.z; fd[7]=v.w;
            v = ed4[0]; ed[0]=v.x; ed[1]=v.y; ed[2]=v.z; ed[3]=v.w;
            v = ed4[1]; ed[4]=v.x; ed[5]=v.y; ed[6]=v.z; ed[7]=v.w;
            v = eb4[0]; eb[0]=v.x; eb[1]=v.y; eb[2]=v.z; eb[3]=v.w;
            v = eb4[1]; eb[4]=v.x; eb[5]=v.y; eb[6]=v.z; eb[7]=v.w;
            #pragma unroll
            for (int hh = 0; hh < 8; hh++) {
                float s = myFs[hh] + fd[hh];
                float p = (s > 0.f) ? (myEi[hh] * ed[hh]) : (myEib[hh] * eb[hh]);
                p = bit ? p : 0.f;
                zloc[hh] += p;
                sP[jj][hh * RI + r] = p;
            }
        }
        __syncthreads();
        // ---- phase B: acc[o][r] += P[q][h][r] * Wh1[j][o], packed pairs ----
        #pragma unroll
        for (int q = 0; q < CJ; q++) {
            unsigned wu = __float_as_uint(wh[q]);
            unsigned long long whd;
            asm("mov.b64 %0, {%1, %1};" : "=l"(whd) : "r"(wu));
            const ulonglong2* pd = (const ulonglong2*)&sP[q][h * RI];
            #pragma unroll
            for (int p8 = 0; p8 < 8; p8++) {
                ulonglong2 d2 = pd[p8];
                asm("fma.rn.f32x2 %0, %1, %2, %0;" : "+l"(acc2[p8 * 2 + 0]) : "l"(d2.x), "l"(whd));
                asm("fma.rn.f32x2 %0, %1, %2, %0;" : "+l"(acc2[p8 * 2 + 1]) : "l"(d2.y), "l"(whd));
            }
        }
        __syncthreads();
    }

    // ---- Z reduction ----
    #pragma unroll
    for (int hh = 0; hh < 8; hh++) atomicAdd(&sZ[r][hh], zloc[hh]);
    __syncthreads();

    // ---- epilogue: normalize + ELU ----
    #pragma unroll
    for (int k = 0; k < 16; k++) {
        unsigned long long a = acc2[k];
        float lo = __uint_as_float((unsigned)(a & 0xffffffffull));
        float hi = __uint_as_float((unsigned)(a >> 32));
        int r0 = k * 2, r1 = k * 2 + 1;
        float v0 = lo / sZ[r0][h];
        float v1 = hi / sZ[r1][h];
        v0 = (v0 > 0.f) ? v0 : (expf(v0) - 1.f);
        v1 = (v1 > 0.f) ? v1 : (expf(v1) - 1.f);
        g_hcat[(size_t)(i0 + r0) * HD + t] = v0;
        g_hcat[(size_t)(i0 + r1) * HD + t] = v1;
    }
}

// ---------------- K3: Wh2 = hcat @ W2, plus layer-2 logits ----------------
__global__ __launch_bounds__(256) void k_l2prep(const float* __restrict__ W2,
                                                const float* __restrict__ a2) {
    __shared__ float sH[16 * NFEAT];   // 32 KB
    __shared__ float sWh[16 * NCLASS];
    int i0 = blockIdx.x * 16;
    int t = threadIdx.x;
    for (int idx = t; idx < 16 * NFEAT; idx += 256)
        sH[idx] = g_hcat[(size_t)i0 * NFEAT + idx];
    __syncthreads();
    int r = t >> 4, c = t & 15;
    float acc = 0.f;
    #pragma unroll 4
    for (int f = 0; f < NFEAT; f++)
        acc += sH[r * NFEAT + f] * W2[f * NCLASS + c];
    g_Wh2[(i0 + r) * NCLASS + c] = acc;
    sWh[r * NCLASS + c] = acc;
    __syncthreads();
    if (t < 16) {
        float fs = 0.f, fd = 0.f;
        #pragma unroll
        for (int c2 = 0; c2 < NCLASS; c2++) {
            float v = sWh[t * NCLASS + c2];
            fs += v * a2[c2];
            fd += v * a2[NCLASS + c2];
        }
        int i = i0 + t;
        g_fs2[i] = fs; g_fd2[i] = fd;
        g_ed2[i] = expf(fd); g_ed2b[i] = expf(0.2f * fd);
    }
}

// ---------------- K4: fused attention layer 2 (no ELU) ----------------
__global__ __launch_bounds__(256) void k_att2(float* __restrict__ out) {
    __shared__ unsigned sAdj[16][128];
    __shared__ float sP2[256 * 17];     // [jj][r], padded
    __shared__ float sZ[16];
    __shared__ float sFs[16], sEi[16], sEib[16];
    int i0 = blockIdx.x * 16;
    int t = threadIdx.x;                // 256
    for (int idx = t; idx < 16 * 128; idx += 256)
        sAdj[idx >> 7][idx & 127] = g_adj[(size_t)(i0 + (idx >> 7)) * 128 + (idx & 127)];
    if (t < 16) {
        float fs = g_fs2[i0 + t];
        sFs[t] = fs; sEi[t] = expf(fs); sEib[t] = expf(0.2f * fs);
        sZ[t] = 0.f;
    }
    __syncthreads();
    int r = t >> 4, c = t & 15;
    float acc = 0.f;
    float zloc[16] = {};
    for (int cbase = 0; cbase < N; cbase += 256) {
        int j = cbase + t;
        float fd = g_fd2[j], ed = g_ed2[j], eb = g_ed2b[j];
        #pragma unroll
        for (int rr = 0; rr < 16; rr++) {
            unsigned bit = (sAdj[rr][j >> 5] >> (j & 31)) & 1u;
            float s = sFs[rr] + fd;
            float p = (s > 0.f) ? (sEi[rr] * ed) : (sEib[rr] * eb);
            p = bit ? p : 0.f;
            zloc[rr] += p;
            sP2[t * 17 + rr] = p;
        }
        __syncthreads();
        #pragma unroll 8
        for (int q = 0; q < 256; q++) {
            float wh = g_Wh2[(size_t)(cbase + q) * NCLASS + c];
            acc += sP2[q * 17 + r] * wh;
        }
        __syncthreads();
    }
    #pragma unroll
    for (int rr = 0; rr < 16; rr++) atomicAdd(&sZ[rr], zloc[rr]);
    __syncthreads();
    out[(size_t)(i0 + r) * NCLASS + c] = acc / sZ[r];
}

// ---------------- launcher ----------------
extern "C" void kernel_launch(void* const* d_in, const int* in_sizes, int n_in,
                              void* d_out, int out_size) {
    const float* x   = (const float*)d_in[0];
    const int*   adj = (const int*)  d_in[1];
    const float* W1  = (const float*)d_in[2];
    const float* a1  = (const float*)d_in[3];
    const float* W2  = (const float*)d_in[4];
    const float* a2  = (const float*)d_in[5];
    float* out = (float*)d_out;

    k_pack<<<N, 1024>>>(adj);
    k_w1r<<<(NHEADS * NFEAT * NHID) / 256, 256>>>(W1);
    k_gemm1<<<dim3(N / 64, HD / 64), 256>>>(x);
    k_logit1<<<N, 256>>>(a1);
    k_att1<<<N / RI, 512>>>();
    k_l2prep<<<N / 16, 256>>>(W2, a2);
    k_att2<<<N / 16, 256>>>(out);
}

// round 12
// speedup vs baseline: 1.9132x; 1.9132x over previous
#include <cuda_runtime.h>
#include <cuda_bf16.h>
#include <math.h>

#define N       4096
#define NFEAT   512
#define NHID    64
#define NHEADS  8
#define NCLASS  16
#define HD      512

// ---------------- scratch ----------------
__device__ unsigned g_adj[N * 128];
__device__ unsigned g_adjT[128 * N];          // [word j>>5][i]
__device__ float g_W1r[NFEAT * HD];
__device__ float g_Wh1[N * HD];
__device__ float g_ei[NHEADS * N], g_eib[NHEADS * N];   // exp(fs), exp(.2fs)
__device__ float g_edj[NHEADS * N], g_ebj[NHEADS * N];  // exp(fd), exp(.2fd)
__device__ unsigned short g_WT_hi[HD * N];    // [col=h*64+n][i]  bf16 hi
__device__ unsigned short g_WT_lo[HD * N];    // [col][i]          bf16 lo
__device__ float g_hcat[N * HD];
__device__ float g_Wh2[N * NCLASS];
__device__ float g_fs2[N], g_fd2[N], g_ed2[N], g_ed2b[N];

__device__ __forceinline__ unsigned sm2u32(const void* p) {
    unsigned a;
    asm("{ .reg .u64 t; cvta.to.shared.u64 t, %1; cvt.u32.u64 %0, t; }" : "=r"(a) : "l"(p));
    return a;
}
#define LDSM4(r, a) asm volatile( \
    "ldmatrix.sync.aligned.m8n8.x4.shared.b16 {%0,%1,%2,%3}, [%4];" \
    : "=r"((r)[0]), "=r"((r)[1]), "=r"((r)[2]), "=r"((r)[3]) : "r"(a))
#define MMA(d, a, b0, b1) asm volatile( \
    "mma.sync.aligned.m16n8k16.row.col.f32.bf16.bf16.f32 " \
    "{%0,%1,%2,%3}, {%4,%5,%6,%7}, {%8,%9}, {%0,%1,%2,%3};" \
    : "+f"((d)[0]), "+f"((d)[1]), "+f"((d)[2]), "+f"((d)[3]) \
    : "r"((a)[0]), "r"((a)[1]), "r"((a)[2]), "r"((a)[3]), "r"(b0), "r"(b1))

// ---------------- K0: adjacency bitmasks (row-major + transposed) ----------------
__global__ void k_pack(const int* __restrict__ adj) {
    int i = blockIdx.x, t = threadIdx.x;
    for (int base = 0; base < N; base += 1024) {
        int j = base + t;
        unsigned m = __ballot_sync(0xffffffffu, adj[(size_t)i * N + j] > 0);
        if ((t & 31) == 0) {
            g_adj[i * 128 + (j >> 5)] = m;
            g_adjT[(size_t)(j >> 5) * N + i] = m;
        }
    }
}

// ---------------- K0b: W1[h][f][k] -> W1r[f][h*64+k] ----------------
__global__ void k_w1r(const float* __restrict__ W1) {
    int idx = blockIdx.x * 256 + threadIdx.x;
    int k = idx & 63, f = (idx >> 6) & 511, h = idx >> 15;
    g_W1r[f * HD + h * 64 + k] = W1[idx];
}

// ---------------- K1: Wh1 = x @ W1r ----------------
__global__ __launch_bounds__(256) void k_gemm1(const float* __restrict__ x) {
    __shared__ __align__(16) float As[16 * 68];
    __shared__ __align__(16) float Bs[16 * 64];
    int m0 = blockIdx.x * 64, n0 = blockIdx.y * 64;
    int t = threadIdx.x, tr = t >> 4, tc = t & 15;
    unsigned long long acc2[4][2] = {};
    for (int kk = 0; kk < NFEAT; kk += 16) {
        {
            int c = t & 15, r0 = t >> 4;
            #pragma unroll
            for (int rr = 0; rr < 4; rr++)
                As[c * 68 + r0 + rr * 16] = x[(size_t)(m0 + r0 + rr * 16) * NFEAT + kk + c];
        }
        {
            int n = t & 63, k0 = t >> 6;
            #pragma unroll
            for (int q = 0; q < 4; q++)
                Bs[(k0 + q * 4) * 64 + n] = g_W1r[(size_t)(kk + k0 + q * 4) * HD + n0 + n];
        }
        __syncthreads();
        #pragma unroll
        for (int k = 0; k < 16; k++) {
            float4 a4 = *(const float4*)&As[k * 68 + tr * 4];
            ulonglong2 b2 = *(const ulonglong2*)&Bs[k * 64 + tc * 4];
            float av[4] = {a4.x, a4.y, a4.z, a4.w};
            #pragma unroll
            for (int i = 0; i < 4; i++) {
                unsigned au = __float_as_uint(av[i]);
                unsigned long long ad;
                asm("mov.b64 %0, {%1, %1};" : "=l"(ad) : "r"(au));
                asm("fma.rn.f32x2 %0, %1, %2, %0;" : "+l"(acc2[i][0]) : "l"(b2.x), "l"(ad));
                asm("fma.rn.f32x2 %0, %1, %2, %0;" : "+l"(acc2[i][1]) : "l"(b2.y), "l"(ad));
            }
        }
        __syncthreads();
    }
    #pragma unroll
    for (int i = 0; i < 4; i++) {
        float4 v;
        v.x = __uint_as_float((unsigned)(acc2[i][0] & 0xffffffffull));
        v.y = __uint_as_float((unsigned)(acc2[i][0] >> 32));
        v.z = __uint_as_float((unsigned)(acc2[i][1] & 0xffffffffull));
        v.w = __uint_as_float((unsigned)(acc2[i][1] >> 32));
        *(float4*)&g_Wh1[(size_t)(m0 + tr * 4 + i) * HD + n0 + tc * 4] = v;
    }
}

// ---------------- K1b: logits -> exp tables (head-major) ----------------
__global__ void k_logit1(const float* __restrict__ a1) {
    int i = blockIdx.x;
    int w = threadIdx.x >> 5, l = threadIdx.x & 31;
    const float* wh = &g_Wh1[(size_t)i * HD + w * 64];
    const float* a  = &a1[w * 128];
    float s = wh[l] * a[l]      + wh[l + 32] * a[l + 32];
    float d = wh[l] * a[64 + l] + wh[l + 32] * a[96 + l];
    #pragma unroll
    for (int o = 16; o; o >>= 1) {
        s += __shfl_xor_sync(0xffffffffu, s, o);
        d += __shfl_xor_sync(0xffffffffu, d, o);
    }
    if (l == 0) {
        int o = w * N + i;
        g_ei[o]  = expf(s); g_eib[o] = expf(0.2f * s);
        g_edj[o] = expf(d); g_ebj[o] = expf(0.2f * d);
    }
}

// ---------------- K1c: WT[col][i] = bf16 hi/lo split of Wh1[i][col] ----------------
__global__ void k_whT(void) {
    __shared__ float tile[32][33];
    int i0 = blockIdx.x * 32, c0 = blockIdx.y * 32;
    int tx = threadIdx.x, ty = threadIdx.y;      // 32 x 8
    #pragma unroll
    for (int q = 0; q < 4; q++)
        tile[ty + q * 8][tx] = g_Wh1[(size_t)(i0 + ty + q * 8) * HD + c0 + tx];
    __syncthreads();
    float v[4];
    #pragma unroll
    for (int k = 0; k < 4; k++) v[k] = tile[ty * 4 + k][tx];
    unsigned h0, h1, l0, l1;
    asm("cvt.rn.bf16x2.f32 %0, %1, %2;" : "=r"(h0) : "f"(v[1]), "f"(v[0]));
    asm("cvt.rn.bf16x2.f32 %0, %1, %2;" : "=r"(h1) : "f"(v[3]), "f"(v[2]));
    float q0 = v[0] - __uint_as_float(h0 << 16);
    float q1 = v[1] - __uint_as_float(h0 & 0xffff0000u);
    float q2 = v[2] - __uint_as_float(h1 << 16);
    float q3 = v[3] - __uint_as_float(h1 & 0xffff0000u);
    asm("cvt.rn.bf16x2.f32 %0, %1, %2;" : "=r"(l0) : "f"(q1), "f"(q0));
    asm("cvt.rn.bf16x2.f32 %0, %1, %2;" : "=r"(l1) : "f"(q3), "f"(q2));
    size_t off = (size_t)(c0 + tx) * N + i0 + ty * 4;
    *(uint2*)&g_WT_hi[off] = make_uint2(h0, h1);
    *(uint2*)&g_WT_lo[off] = make_uint2(l0, l1);
}

// ---------------- K2: layer-1 attention via mma.sync bf16 hi/lo ----------------
// CTA = (head, 128 rows), 8 warps; warp w owns m-rows w*16..+15.
// Chunk = 32 j. Build masked P[128x32] bf16 hi/lo into SMEM (stride 40),
// stage B = WhT[64n x 32j] hi/lo, then 2 k-steps x 8 n-tiles x 3 split-MMAs.
#define PSTR 40
__global__ __launch_bounds__(256) void k_att1_mma(void) {
    __shared__ __align__(16) unsigned short sPh[128 * PSTR], sPl[128 * PSTR];
    __shared__ __align__(16) unsigned short sBh[64 * PSTR], sBl[64 * PSTR];
    __shared__ __align__(16) float sEd[32], sEb[32];
    __shared__ float zbuf[256];

    int t = threadIdx.x, lane = t & 31, w = t >> 5;
    int head = blockIdx.x & 7, i0 = (blockIdx.x >> 3) * 128;
    int r = t & 127, jh = t >> 7;                   // build ids
    int m0 = w * 16;

    float ei  = g_ei [head * N + i0 + r];
    float eib = g_eib[head * N + i0 + r];
    unsigned pBh = sm2u32(sPh), pBl = sm2u32(sPl);
    unsigned bBh = sm2u32(sBh), bBl = sm2u32(sBl);

    // ldmatrix lane offsets (bytes)
    int rowA = m0 + (lane & 7) + ((lane >> 3) & 1) * 8;
    unsigned aoff = (unsigned)(rowA * PSTR + ((lane >> 4) & 1) * 8) * 2;
    unsigned boff = (unsigned)(((lane & 7) + ((lane >> 4) & 1) * 8) * PSTR
                               + ((lane >> 3) & 1) * 8) * 2;

    float acc[8][4];
    #pragma unroll
    for (int q = 0; q < 8; q++)
        #pragma unroll
        for (int k = 0; k < 4; k++) acc[q][k] = 0.f;
    float zl = 0.f;

    for (int c = 0; c < 128; c++) {
        // ---- stage exp tables + B tile ----
        if (t < 32)       sEd[t]      = g_edj[head * N + c * 32 + t];
        else if (t < 64)  sEb[t - 32] = g_ebj[head * N + c * 32 + (t - 32)];
        {
            int n = t >> 2, part = t & 3;
            size_t go = (size_t)(head * 64 + n) * N + c * 32 + part * 8;
            *(uint4*)&sBh[n * PSTR + part * 8] = *(const uint4*)&g_WT_hi[go];
            *(uint4*)&sBl[n * PSTR + part * 8] = *(const uint4*)&g_WT_lo[go];
        }
        __syncthreads();
        // ---- build masked P (16 j per thread) ----
        {
            unsigned bits = g_adjT[(size_t)c * N + i0 + r] >> (jh * 16);
            #pragma unroll
            for (int u = 0; u < 4; u++) {
                float4 e = ((const float4*)sEd)[jh * 4 + u];
                float4 b = ((const float4*)sEb)[jh * 4 + u];
                float p0 = fmaxf(ei * e.x, eib * b.x);
                float p1 = fmaxf(ei * e.y, eib * b.y);
                float p2 = fmaxf(ei * e.z, eib * b.z);
                float p3 = fmaxf(ei * e.w, eib * b.w);
                p0 = ((bits >> (u * 4 + 0)) & 1u) ? p0 : 0.f;
                p1 = ((bits >> (u * 4 + 1)) & 1u) ? p1 : 0.f;
                p2 = ((bits >> (u * 4 + 2)) & 1u) ? p2 : 0.f;
                p3 = ((bits >> (u * 4 + 3)) & 1u) ? p3 : 0.f;
                zl += (p0 + p1) + (p2 + p3);
                unsigned h0, h1, l0, l1;
                asm("cvt.rn.bf16x2.f32 %0, %1, %2;" : "=r"(h0) : "f"(p1), "f"(p0));
                asm("cvt.rn.bf16x2.f32 %0, %1, %2;" : "=r"(h1) : "f"(p3), "f"(p2));
                float q0 = p0 - __uint_as_float(h0 << 16);
                float q1 = p1 - __uint_as_float(h0 & 0xffff0000u);
                float q2 = p2 - __uint_as_float(h1 << 16);
                float q3 = p3 - __uint_as_float(h1 & 0xffff0000u);
                asm("cvt.rn.bf16x2.f32 %0, %1, %2;" : "=r"(l0) : "f"(q1), "f"(q0));
                asm("cvt.rn.bf16x2.f32 %0, %1, %2;" : "=r"(l1) : "f"(q3), "f"(q2));
                int o = r * PSTR + jh * 16 + u * 4;
                *(uint2*)&sPh[o] = make_uint2(h0, h1);
                *(uint2*)&sPl[o] = make_uint2(l0, l1);
            }
        }
        __syncthreads();
        // ---- mma: 2 k-steps x 4 n-groups x (2 n-tiles x 3 splits) ----
        #pragma unroll
        for (int ks = 0; ks < 2; ks++) {
            unsigned Ah[4], Al[4];
            LDSM4(Ah, pBh + aoff + ks * 32);
            LDSM4(Al, pBl + aoff + ks * 32);
            #pragma unroll
            for (int g = 0; g < 4; g++) {
                unsigned Bh[4], Bl[4];
                unsigned bo = boff + g * (16 * PSTR * 2) + ks * 32;
                LDSM4(Bh, bBh + bo);
                LDSM4(Bl, bBl + bo);
                MMA(acc[g * 2 + 0], Ah, Bh[0], Bh[1]);
                MMA(acc[g * 2 + 0], Ah, Bl[0], Bl[1]);
                MMA(acc[g * 2 + 0], Al, Bh[0], Bh[1]);
                MMA(acc[g * 2 + 1], Ah, Bh[2], Bh[3]);
                MMA(acc[g * 2 + 1], Ah, Bl[2], Bl[3]);
                MMA(acc[g * 2 + 1], Al, Bh[2], Bh[3]);
            }
        }
        __syncthreads();
    }

    zbuf[t] = zl;
    __syncthreads();

    // ---- epilogue: /Z, ELU, store ----
    int rr0 = m0 + (lane >> 2), rr1 = rr0 + 8;
    float z0 = 1.f / (zbuf[rr0] + zbuf[rr0 + 128]);
    float z1 = 1.f / (zbuf[rr1] + zbuf[rr1 + 128]);
    float* d0 = &g_hcat[(size_t)(i0 + rr0) * HD + head * 64 + (lane & 3) * 2];
    float* d1 = &g_hcat[(size_t)(i0 + rr1) * HD + head * 64 + (lane & 3) * 2];
    #pragma unroll
    for (int nt = 0; nt < 8; nt++) {
        float v0 = acc[nt][0] * z0, v1 = acc[nt][1] * z0;
        float v2 = acc[nt][2] * z1, v3 = acc[nt][3] * z1;
        v0 = (v0 > 0.f) ? v0 : (expf(v0) - 1.f);
        v1 = (v1 > 0.f) ? v1 : (expf(v1) - 1.f);
        v2 = (v2 > 0.f) ? v2 : (expf(v2) - 1.f);
        v3 = (v3 > 0.f) ? v3 : (expf(v3) - 1.f);
        *(float2*)(d0 + nt * 8) = make_float2(v0, v1);
        *(float2*)(d1 + nt * 8) = make_float2(v2, v3);
    }
}

// ---------------- K3: Wh2 = hcat @ W2 + layer-2 logits ----------------
__global__ __launch_bounds__(256) void k_l2prep(const float* __restrict__ W2,
                                                const float* __restrict__ a2) {
    __shared__ float sH[16 * NFEAT];
    __shared__ float sWh[16 * NCLASS];
    int i0 = blockIdx.x * 16, t = threadIdx.x;
    for (int idx = t; idx < 16 * NFEAT; idx += 256)
        sH[idx] = g_hcat[(size_t)i0 * NFEAT + idx];
    __syncthreads();
    int r = t >> 4, c = t & 15;
    float acc = 0.f;
    #pragma unroll 4
    for (int f = 0; f < NFEAT; f++)
        acc += sH[r * NFEAT + f] * W2[f * NCLASS + c];
    g_Wh2[(i0 + r) * NCLASS + c] = acc;
    sWh[r * NCLASS + c] = acc;
    __syncthreads();
    if (t < 16) {
        float fs = 0.f, fd = 0.f;
        #pragma unroll
        for (int c2 = 0; c2 < NCLASS; c2++) {
            float v = sWh[t * NCLASS + c2];
            fs += v * a2[c2];
            fd += v * a2[NCLASS + c2];
        }
        int i = i0 + t;
        g_fs2[i] = fs; g_fd2[i] = fd;
        g_ed2[i] = expf(fd); g_ed2b[i] = expf(0.2f * fd);
    }
}

// ---------------- K4: layer-2 attention (no ELU) ----------------
__global__ __launch_bounds__(256) void k_att2(float* __restrict__ out) {
    __shared__ unsigned sAdj[16][128];
    __shared__ float sP2[256 * 17];
    __shared__ float sZ[16];
    __shared__ float sFs[16], sEi[16], sEib[16];
    int i0 = blockIdx.x * 16, t = threadIdx.x;
    for (int idx = t; idx < 16 * 128; idx += 256)
        sAdj[idx >> 7][idx & 127] = g_adj[(size_t)(i0 + (idx >> 7)) * 128 + (idx & 127)];
    if (t < 16) {
        float fs = g_fs2[i0 + t];
        sFs[t] = fs; sEi[t] = expf(fs); sEib[t] = expf(0.2f * fs);
        sZ[t] = 0.f;
    }
    __syncthreads();
    int r = t >> 4, c = t & 15;
    float acc = 0.f, zloc[16] = {};
    for (int cbase = 0; cbase < N; cbase += 256) {
        int j = cbase + t;
        float fd = g_fd2[j], ed = g_ed2[j], eb = g_ed2b[j];
        #pragma unroll
        for (int rr = 0; rr < 16; rr++) {
            unsigned bit = (sAdj[rr][j >> 5] >> (j & 31)) & 1u;
            float s = sFs[rr] + fd;
            float p = (s > 0.f) ? (sEi[rr] * ed) : (sEib[rr] * eb);
            p = bit ? p : 0.f;
            zloc[rr] += p;
            sP2[t * 17 + rr] = p;
        }
        __syncthreads();
        #pragma unroll 8
        for (int q = 0; q < 256; q++)
            acc += sP2[q * 17 + r] * g_Wh2[(size_t)(cbase + q) * NCLASS + c];
        __syncthreads();
    }
    #pragma unroll
    for (int rr = 0; rr < 16; rr++) atomicAdd(&sZ[rr], zloc[rr]);
    __syncthreads();
    out[(size_t)(i0 + r) * NCLASS + c] = acc / sZ[r];
}

// ---------------- launcher ----------------
extern "C" void kernel_launch(void* const* d_in, const int* in_sizes, int n_in,
                              void* d_out, int out_size) {
    const float* x   = (const float*)d_in[0];
    const int*   adj = (const int*)  d_in[1];
    const float* W1  = (const float*)d_in[2];
    const float* a1  = (const float*)d_in[3];
    const float* W2  = (const float*)d_in[4];
    const float* a2  = (const float*)d_in[5];
    float* out = (float*)d_out;

    k_pack<<<N, 1024>>>(adj);
    k_w1r<<<(NHEADS * NFEAT * NHID) / 256, 256>>>(W1);
    k_gemm1<<<dim3(N / 64, HD / 64), 256>>>(x);
    k_logit1<<<N, 256>>>(a1);
    k_whT<<<dim3(N / 32, HD / 32), dim3(32, 8)>>>();
    k_att1_mma<<<256, 256>>>();
    k_l2prep<<<N / 16, 256>>>(W2, a2);
    k_att2<<<N / 16, 256>>>(out);
}

// round 13
// speedup vs baseline: 1.9735x; 1.0315x over previous
#include <cuda_runtime.h>
#include <cuda_bf16.h>
#include <math.h>

#define N       4096
#define NFEAT   512
#define NHID    64
#define NHEADS  8
#define NCLASS  16
#define HD      512

// ---------------- scratch ----------------
__device__ unsigned g_adj[N * 128];
__device__ unsigned g_adjT[128 * N];          // [word j>>5][i]
__device__ float g_Wh1[N * HD];
__device__ float g_ei[NHEADS * N], g_eib[NHEADS * N];   // exp(fs), exp(.2fs)
__device__ float g_edj[NHEADS * N], g_ebj[NHEADS * N];  // exp(fd), exp(.2fd)
__device__ unsigned short g_WT_hi[HD * N];    // [col=h*64+n][i]  bf16 hi
__device__ unsigned short g_WT_lo[HD * N];    // [col][i]         bf16 lo
__device__ float g_hcat[N * HD];
__device__ float g_Wh2[N * NCLASS];
__device__ float g_fs2[N], g_fd2[N], g_ed2[N], g_ed2b[N];

__device__ __forceinline__ unsigned sm2u32(const void* p) {
    unsigned a;
    asm("{ .reg .u64 t; cvta.to.shared.u64 t, %1; cvt.u32.u64 %0, t; }" : "=r"(a) : "l"(p));
    return a;
}
#define LDSM4(r, a) asm volatile( \
    "ldmatrix.sync.aligned.m8n8.x4.shared.b16 {%0,%1,%2,%3}, [%4];" \
    : "=r"((r)[0]), "=r"((r)[1]), "=r"((r)[2]), "=r"((r)[3]) : "r"(a))
#define MMA(d, a, b0, b1) asm volatile( \
    "mma.sync.aligned.m16n8k16.row.col.f32.bf16.bf16.f32 " \
    "{%0,%1,%2,%3}, {%4,%5,%6,%7}, {%8,%9}, {%0,%1,%2,%3};" \
    : "+f"((d)[0]), "+f"((d)[1]), "+f"((d)[2]), "+f"((d)[3]) \
    : "r"((a)[0]), "r"((a)[1]), "r"((a)[2]), "r"((a)[3]), "r"(b0), "r"(b1))

// ---------------- K0: adjacency bitmasks ----------------
__global__ void k_pack(const int* __restrict__ adj) {
    int i = blockIdx.x, t = threadIdx.x;
    for (int base = 0; base < N; base += 1024) {
        int j = base + t;
        unsigned m = __ballot_sync(0xffffffffu, adj[(size_t)i * N + j] > 0);
        if ((t & 31) == 0) {
            g_adj[i * 128 + (j >> 5)] = m;
            g_adjT[(size_t)(j >> 5) * N + i] = m;
        }
    }
}

// ---------------- K1: Wh1 = x @ W1 (direct indexing, no pre-rearrange) ----------------
__global__ __launch_bounds__(256) void k_gemm1(const float* __restrict__ x,
                                               const float* __restrict__ W1) {
    __shared__ __align__(16) float As[16 * 68];
    __shared__ __align__(16) float Bs[16 * 64];
    int m0 = blockIdx.x * 64, n0 = blockIdx.y * 64;
    int t = threadIdx.x, tr = t >> 4, tc = t & 15;
    // W1r[f][n] with n=n0+nn -> W1[(h*512+f)*64 + k2], h=n>>6 const per block
    int hh = n0 >> 6;
    unsigned long long acc2[4][2] = {};
    for (int kk = 0; kk < NFEAT; kk += 16) {
        {
            int c = t & 15, r0 = t >> 4;
            #pragma unroll
            for (int rr = 0; rr < 4; rr++)
                As[c * 68 + r0 + rr * 16] = x[(size_t)(m0 + r0 + rr * 16) * NFEAT + kk + c];
        }
        {
            int nn = t & 63, k0 = t >> 6;
            #pragma unroll
            for (int q = 0; q < 4; q++) {
                int f = kk + k0 + q * 4;
                Bs[(k0 + q * 4) * 64 + nn] = W1[((size_t)hh * 512 + f) * 64 + nn];
            }
        }
        __syncthreads();
        #pragma unroll
        for (int k = 0; k < 16; k++) {
            float4 a4 = *(const float4*)&As[k * 68 + tr * 4];
            ulonglong2 b2 = *(const ulonglong2*)&Bs[k * 64 + tc * 4];
            float av[4] = {a4.x, a4.y, a4.z, a4.w};
            #pragma unroll
            for (int i = 0; i < 4; i++) {
                unsigned au = __float_as_uint(av[i]);
                unsigned long long ad;
                asm("mov.b64 %0, {%1, %1};" : "=l"(ad) : "r"(au));
                asm("fma.rn.f32x2 %0, %1, %2, %0;" : "+l"(acc2[i][0]) : "l"(b2.x), "l"(ad));
                asm("fma.rn.f32x2 %0, %1, %2, %0;" : "+l"(acc2[i][1]) : "l"(b2.y), "l"(ad));
            }
        }
        __syncthreads();
    }
    #pragma unroll
    for (int i = 0; i < 4; i++) {
        float4 v;
        v.x = __uint_as_float((unsigned)(acc2[i][0] & 0xffffffffull));
        v.y = __uint_as_float((unsigned)(acc2[i][0] >> 32));
        v.z = __uint_as_float((unsigned)(acc2[i][1] & 0xffffffffull));
        v.w = __uint_as_float((unsigned)(acc2[i][1] >> 32));
        *(float4*)&g_Wh1[(size_t)(m0 + tr * 4 + i) * HD + n0 + tc * 4] = v;
    }
}

// ---------------- K2: merged logits + transpose-split (was k_logit1 + k_whT) ----------------
__global__ __launch_bounds__(256) void k_post(const float* __restrict__ a1p) {
    __shared__ float tile[32][33];
    int i0 = blockIdx.x * 32;
    int t = threadIdx.x, w = t >> 5, l = t & 31;
    // --- logits: warp w = head w ---
    {
        const float* a = &a1p[w * 128];
        float as0 = a[l], as1 = a[l + 32], ad0 = a[64 + l], ad1 = a[96 + l];
        for (int rr = 0; rr < 32; rr++) {
            const float* wh = &g_Wh1[(size_t)(i0 + rr) * HD + w * 64];
            float s = wh[l] * as0 + wh[l + 32] * as1;
            float d = wh[l] * ad0 + wh[l + 32] * ad1;
            #pragma unroll
            for (int o = 16; o; o >>= 1) {
                s += __shfl_xor_sync(0xffffffffu, s, o);
                d += __shfl_xor_sync(0xffffffffu, d, o);
            }
            if (l == 0) {
                int o = w * N + i0 + rr;
                g_ei[o]  = expf(s); g_eib[o] = expf(0.2f * s);
                g_edj[o] = expf(d); g_ebj[o] = expf(0.2f * d);
            }
        }
    }
    // --- transpose + bf16 hi/lo split, 16 column-chunks ---
    int tx = t & 31, ty = t >> 5;
    for (int cc = 0; cc < 16; cc++) {
        int c0 = cc * 32;
        __syncthreads();
        #pragma unroll
        for (int q = 0; q < 4; q++)
            tile[ty + q * 8][tx] = g_Wh1[(size_t)(i0 + ty + q * 8) * HD + c0 + tx];
        __syncthreads();
        float v[4];
        #pragma unroll
        for (int k = 0; k < 4; k++) v[k] = tile[ty * 4 + k][tx];
        unsigned h0, h1, l0, l1;
        asm("cvt.rn.bf16x2.f32 %0, %1, %2;" : "=r"(h0) : "f"(v[1]), "f"(v[0]));
        asm("cvt.rn.bf16x2.f32 %0, %1, %2;" : "=r"(h1) : "f"(v[3]), "f"(v[2]));
        float q0 = v[0] - __uint_as_float(h0 << 16);
        float q1 = v[1] - __uint_as_float(h0 & 0xffff0000u);
        float q2 = v[2] - __uint_as_float(h1 << 16);
        float q3 = v[3] - __uint_as_float(h1 & 0xffff0000u);
        asm("cvt.rn.bf16x2.f32 %0, %1, %2;" : "=r"(l0) : "f"(q1), "f"(q0));
        asm("cvt.rn.bf16x2.f32 %0, %1, %2;" : "=r"(l1) : "f"(q3), "f"(q2));
        size_t off = (size_t)(c0 + tx) * N + i0 + ty * 4;
        *(uint2*)&g_WT_hi[off] = make_uint2(h0, h1);
        *(uint2*)&g_WT_lo[off] = make_uint2(l0, l1);
    }
}

// ---------------- K3: layer-1 attention via mma.sync, pipelined ----------------
// CTA = (head, 128 rows), 8 warps. Chunk = 32 j.
// Pipeline: regs hold chunk c's staged data at loop top (prefetched during c-1);
// STS -> sync -> build P -> sync -> MMA. B SMEM double-buffered (MMA(c-1) may
// still read while staging c). P + exp single-buffered (safe across the 2 barriers).
#define PSTR 40
__global__ __launch_bounds__(256, 2) void k_att1_mma(void) {
    __shared__ __align__(16) unsigned short sPh[128 * PSTR], sPl[128 * PSTR];
    __shared__ __align__(16) unsigned short sBh[2][64 * PSTR], sBl[2][64 * PSTR];
    __shared__ __align__(16) float sEd[32], sEb[32];
    __shared__ float zbuf[256];

    int t = threadIdx.x, lane = t & 31, w = t >> 5;
    int head = blockIdx.x & 7, i0 = (blockIdx.x >> 3) * 128;
    int r = t & 127, jh = t >> 7;
    int m0 = w * 16;

    float ei  = g_ei [head * N + i0 + r];
    float eib = g_eib[head * N + i0 + r];
    unsigned pBh = sm2u32(sPh), pBl = sm2u32(sPl);
    unsigned bBh = sm2u32(sBh), bBl = sm2u32(sBl);

    int rowA = m0 + (lane & 7) + ((lane >> 3) & 1) * 8;
    unsigned aoff = (unsigned)(rowA * PSTR + ((lane >> 4) & 1) * 8) * 2;
    unsigned boff = (unsigned)(((lane & 7) + ((lane >> 4) & 1) * 8) * PSTR
                               + ((lane >> 3) & 1) * 8) * 2;

    // staging identity: thread -> (n = t>>2, part = t&3), one uint4 hi + lo
    int sn = t >> 2, sp = t & 3;
    const uint4* gwh = (const uint4*)&g_WT_hi[(size_t)(head * 64 + sn) * N] + sp;
    const uint4* gwl = (const uint4*)&g_WT_lo[(size_t)(head * 64 + sn) * N] + sp;

    float acc[8][4];
    #pragma unroll
    for (int q = 0; q < 8; q++)
        #pragma unroll
        for (int k = 0; k < 4; k++) acc[q][k] = 0.f;
    float zl = 0.f;

    // prefetch chunk 0
    uint4 rbh = gwh[0], rbl = gwl[0];
    float rexp = (t < 32) ? g_edj[head * N + t]
               : (t < 64) ? g_ebj[head * N + (t - 32)] : 0.f;
    unsigned radj = g_adjT[(size_t)0 * N + i0 + r];

    for (int c = 0; c < 128; c++) {
        int buf = c & 1;
        // ---- STS staged chunk c ----
        *(uint4*)&sBh[buf][sn * PSTR + sp * 8] = rbh;
        *(uint4*)&sBl[buf][sn * PSTR + sp * 8] = rbl;
        if (t < 32) sEd[t] = rexp; else if (t < 64) sEb[t - 32] = rexp;
        unsigned bits = radj >> (jh * 16);
        // ---- prefetch chunk c+1 (in flight across build + MMA) ----
        if (c + 1 < 128) {
            rbh = gwh[(c + 1) * 4];
            rbl = gwl[(c + 1) * 4];
            if (t < 64)
                rexp = (t < 32) ? g_edj[head * N + (c + 1) * 32 + t]
                                : g_ebj[head * N + (c + 1) * 32 + (t - 32)];
            radj = g_adjT[(size_t)(c + 1) * N + i0 + r];
        }
        __syncthreads();
        // ---- build masked P (16 j per thread) ----
        {
            #pragma unroll
            for (int u = 0; u < 4; u++) {
                float4 e = ((const float4*)sEd)[jh * 4 + u];
                float4 b = ((const float4*)sEb)[jh * 4 + u];
                float p0 = fmaxf(ei * e.x, eib * b.x);
                float p1 = fmaxf(ei * e.y, eib * b.y);
                float p2 = fmaxf(ei * e.z, eib * b.z);
                float p3 = fmaxf(ei * e.w, eib * b.w);
                p0 = ((bits >> (u * 4 + 0)) & 1u) ? p0 : 0.f;
                p1 = ((bits >> (u * 4 + 1)) & 1u) ? p1 : 0.f;
                p2 = ((bits >> (u * 4 + 2)) & 1u) ? p2 : 0.f;
                p3 = ((bits >> (u * 4 + 3)) & 1u) ? p3 : 0.f;
                zl += (p0 + p1) + (p2 + p3);
                unsigned h0, h1, l0, l1;
                asm("cvt.rn.bf16x2.f32 %0, %1, %2;" : "=r"(h0) : "f"(p1), "f"(p0));
                asm("cvt.rn.bf16x2.f32 %0, %1, %2;" : "=r"(h1) : "f"(p3), "f"(p2));
                float q0 = p0 - __uint_as_float(h0 << 16);
                float q1 = p1 - __uint_as_float(h0 & 0xffff0000u);
                float q2 = p2 - __uint_as_float(h1 << 16);
                float q3 = p3 - __uint_as_float(h1 & 0xffff0000u);
                asm("cvt.rn.bf16x2.f32 %0, %1, %2;" : "=r"(l0) : "f"(q1), "f"(q0));
                asm("cvt.rn.bf16x2.f32 %0, %1, %2;" : "=r"(l1) : "f"(q3), "f"(q2));
                int o = r * PSTR + jh * 16 + u * 4;
                *(uint2*)&sPh[o] = make_uint2(h0, h1);
                *(uint2*)&sPl[o] = make_uint2(l0, l1);
            }
        }
        __syncthreads();
        // ---- MMA: interleaved accumulators (RAW distance 4) ----
        unsigned bB = (unsigned)(buf * 64 * PSTR * 2);
        #pragma unroll
        for (int ks = 0; ks < 2; ks++) {
            unsigned Ah[4], Al[4];
            LDSM4(Ah, pBh + aoff + ks * 32);
            LDSM4(Al, pBl + aoff + ks * 32);
            #pragma unroll
            for (int gp = 0; gp < 2; gp++) {
                unsigned B0h[4], B0l[4], B1h[4], B1l[4];
                unsigned bo0 = boff + (gp * 2 + 0) * (16 * PSTR * 2) + ks * 32;
                unsigned bo1 = boff + (gp * 2 + 1) * (16 * PSTR * 2) + ks * 32;
                LDSM4(B0h, bBh + bB + bo0);
                LDSM4(B1h, bBh + bB + bo1);
                LDSM4(B0l, bBl + bB + bo0);
                LDSM4(B1l, bBl + bB + bo1);
                float *a0 = acc[gp * 4 + 0], *a1 = acc[gp * 4 + 1];
                float *a2 = acc[gp * 4 + 2], *a3 = acc[gp * 4 + 3];
                MMA(a0, Ah, B0h[0], B0h[1]); MMA(a1, Ah, B0h[2], B0h[3]);
                MMA(a2, Ah, B1h[0], B1h[1]); MMA(a3, Ah, B1h[2], B1h[3]);
                MMA(a0, Al, B0h[0], B0h[1]); MMA(a1, Al, B0h[2], B0h[3]);
                MMA(a2, Al, B1h[0], B1h[1]); MMA(a3, Al, B1h[2], B1h[3]);
                MMA(a0, Ah, B0l[0], B0l[1]); MMA(a1, Ah, B0l[2], B0l[3]);
                MMA(a2, Ah, B1l[0], B1l[1]); MMA(a3, Ah, B1l[2], B1l[3]);
            }
        }
        __syncthreads();
    }

    zbuf[t] = zl;
    __syncthreads();

    // ---- epilogue: /Z, ELU, store ----
    int rr0 = m0 + (lane >> 2), rr1 = rr0 + 8;
    float z0 = 1.f / (zbuf[rr0] + zbuf[rr0 + 128]);
    float z1 = 1.f / (zbuf[rr1] + zbuf[rr1 + 128]);
    float* d0 = &g_hcat[(size_t)(i0 + rr0) * HD + head * 64 + (lane & 3) * 2];
    float* d1 = &g_hcat[(size_t)(i0 + rr1) * HD + head * 64 + (lane & 3) * 2];
    #pragma unroll
    for (int nt = 0; nt < 8; nt++) {
        float v0 = acc[nt][0] * z0, v1 = acc[nt][1] * z0;
        float v2 = acc[nt][2] * z1, v3 = acc[nt][3] * z1;
        v0 = (v0 > 0.f) ? v0 : (expf(v0) - 1.f);
        v1 = (v1 > 0.f) ? v1 : (expf(v1) - 1.f);
        v2 = (v2 > 0.f) ? v2 : (expf(v2) - 1.f);
        v3 = (v3 > 0.f) ? v3 : (expf(v3) - 1.f);
        *(float2*)(d0 + nt * 8) = make_float2(v0, v1);
        *(float2*)(d1 + nt * 8) = make_float2(v2, v3);
    }
}

// ---------------- K4: Wh2 = hcat @ W2 + layer-2 logits ----------------
__global__ __launch_bounds__(256) void k_l2prep(const float* __restrict__ W2,
                                                const float* __restrict__ a2) {
    __shared__ float sH[16 * NFEAT];
    __shared__ float sWh[16 * NCLASS];
    int i0 = blockIdx.x * 16, t = threadIdx.x;
    for (int idx = t; idx < 16 * NFEAT; idx += 256)
        sH[idx] = g_hcat[(size_t)i0 * NFEAT + idx];
    __syncthreads();
    int r = t >> 4, c = t & 15;
    float acc = 0.f;
    #pragma unroll 4
    for (int f = 0; f < NFEAT; f++)
        acc += sH[r * NFEAT + f] * W2[f * NCLASS + c];
    g_Wh2[(i0 + r) * NCLASS + c] = acc;
    sWh[r * NCLASS + c] = acc;
    __syncthreads();
    if (t < 16) {
        float fs = 0.f, fd = 0.f;
        #pragma unroll
        for (int c2 = 0; c2 < NCLASS; c2++) {
            float v = sWh[t * NCLASS + c2];
            fs += v * a2[c2];
            fd += v * a2[NCLASS + c2];
        }
        int i = i0 + t;
        g_fs2[i] = fs; g_fd2[i] = fd;
        g_ed2[i] = expf(fd); g_ed2b[i] = expf(0.2f * fd);
    }
}

// ---------------- K5: layer-2 attention (no ELU) ----------------
__global__ __launch_bounds__(256) void k_att2(float* __restrict__ out) {
    __shared__ unsigned sAdj[16][128];
    __shared__ float sP2[256 * 17];
    __shared__ float sZ[16];
    __shared__ float sFs[16], sEi[16], sEib[16];
    int i0 = blockIdx.x * 16, t = threadIdx.x;
    for (int idx = t; idx < 16 * 128; idx += 256)
        sAdj[idx >> 7][idx & 127] = g_adj[(size_t)(i0 + (idx >> 7)) * 128 + (idx & 127)];
    if (t < 16) {
        float fs = g_fs2[i0 + t];
        sFs[t] = fs; sEi[t] = expf(fs); sEib[t] = expf(0.2f * fs);
        sZ[t] = 0.f;
    }
    __syncthreads();
    int r = t >> 4, c = t & 15;
    float acc = 0.f, zloc[16] = {};
    for (int cbase = 0; cbase < N; cbase += 256) {
        int j = cbase + t;
        float fd = g_fd2[j], ed = g_ed2[j], eb = g_ed2b[j];
        #pragma unroll
        for (int rr = 0; rr < 16; rr++) {
            unsigned bit = (sAdj[rr][j >> 5] >> (j & 31)) & 1u;
            float s = sFs[rr] + fd;
            float p = (s > 0.f) ? (sEi[rr] * ed) : (sEib[rr] * eb);
            p = bit ? p : 0.f;
            zloc[rr] += p;
            sP2[t * 17 + rr] = p;
        }
        __syncthreads();
        #pragma unroll 8
        for (int q = 0; q < 256; q++)
            acc += sP2[q * 17 + r] * g_Wh2[(size_t)(cbase + q) * NCLASS + c];
        __syncthreads();
    }
    #pragma unroll
    for (int rr = 0; rr < 16; rr++) atomicAdd(&sZ[rr], zloc[rr]);
    __syncthreads();
    out[(size_t)(i0 + r) * NCLASS + c] = acc / sZ[r];
}

// ---------------- launcher ----------------
extern "C" void kernel_launch(void* const* d_in, const int* in_sizes, int n_in,
                              void* d_out, int out_size) {
    const float* x   = (const float*)d_in[0];
    const int*   adj = (const int*)  d_in[1];
    const float* W1  = (const float*)d_in[2];
    const float* a1  = (const float*)d_in[3];
    const float* W2  = (const float*)d_in[4];
    const float* a2  = (const float*)d_in[5];
    float* out = (float*)d_out;

    k_pack<<<N, 1024>>>(adj);                       // launch 0
    k_gemm1<<<dim3(N / 64, HD / 64), 256>>>(x, W1); // launch 1
    k_post<<<N / 32, 256>>>(a1);                    // launch 2
    k_att1_mma<<<256, 256>>>();                     // launch 3  <- profiled slot
    k_l2prep<<<N / 16, 256>>>(W2, a2);              // launch 4
    k_att2<<<N / 16, 256>>>(out);                   // launch 5
}

// round 16
// speedup vs baseline: 2.8489x; 1.4436x over previous
#include <cuda_runtime.h>
#include <cuda_bf16.h>
#include <math.h>

#define N       4096
#define NFEAT   512
#define NHID    64
#define NHEADS  8
#define NCLASS  16
#define HD      512

// ---------------- scratch ----------------
__device__ unsigned g_adjT[128 * N];          // [word j>>5][i]
__device__ float g_Wh1[N * HD];
__device__ float g_ei[NHEADS * N], g_eib[NHEADS * N];   // exp(fs), exp(.2fs)
__device__ float g_edj[NHEADS * N], g_ebj[NHEADS * N];  // exp(fd), exp(.2fd)
__device__ unsigned short g_WT_hi[HD * N];    // [col=h*64+n][i]  bf16 hi
__device__ unsigned short g_WT_lo[HD * N];    // [col][i]         bf16 lo
__device__ float g_hcat[N * HD];
__device__ float g_ei2[N], g_eib2[N], g_ed2[N], g_ed2b[N];
__device__ unsigned short g_WT2_hi[NCLASS * N];  // [c][i] bf16 hi of Wh2
__device__ unsigned short g_WT2_lo[NCLASS * N];

__device__ __forceinline__ unsigned sm2u32(const void* p) {
    unsigned a;
    asm("{ .reg .u64 t; cvta.to.shared.u64 t, %1; cvt.u32.u64 %0, t; }" : "=r"(a) : "l"(p));
    return a;
}
#define LDSM4(r, a) asm volatile( \
    "ldmatrix.sync.aligned.m8n8.x4.shared.b16 {%0,%1,%2,%3}, [%4];" \
    : "=r"((r)[0]), "=r"((r)[1]), "=r"((r)[2]), "=r"((r)[3]) : "r"(a))
#define MMA(d, a, b0, b1) asm volatile( \
    "mma.sync.aligned.m16n8k16.row.col.f32.bf16.bf16.f32 " \
    "{%0,%1,%2,%3}, {%4,%5,%6,%7}, {%8,%9}, {%0,%1,%2,%3};" \
    : "+f"((d)[0]), "+f"((d)[1]), "+f"((d)[2]), "+f"((d)[3]) \
    : "r"((a)[0]), "r"((a)[1]), "r"((a)[2]), "r"((a)[3]), "r"(b0), "r"(b1))

// ---------------- K0: transposed adjacency bitmask ----------------
__global__ void k_pack(const int* __restrict__ adj) {
    int i = blockIdx.x, t = threadIdx.x;
    for (int base = 0; base < N; base += 1024) {
        int j = base + t;
        unsigned m = __ballot_sync(0xffffffffu, adj[(size_t)i * N + j] > 0);
        if ((t & 31) == 0) g_adjT[(size_t)(j >> 5) * N + i] = m;
    }
}

// ---------------- K1: Wh1 = x @ W1 ----------------
__global__ __launch_bounds__(256) void k_gemm1(const float* __restrict__ x,
                                               const float* __restrict__ W1) {
    __shared__ __align__(16) float As[16 * 68];
    __shared__ __align__(16) float Bs[16 * 64];
    int m0 = blockIdx.x * 64, n0 = blockIdx.y * 64;
    int t = threadIdx.x, tr = t >> 4, tc = t & 15;
    int hh = n0 >> 6;
    unsigned long long acc2[4][2] = {};
    for (int kk = 0; kk < NFEAT; kk += 16) {
        {
            int c = t & 15, r0 = t >> 4;
            #pragma unroll
            for (int rr = 0; rr < 4; rr++)
                As[c * 68 + r0 + rr * 16] = x[(size_t)(m0 + r0 + rr * 16) * NFEAT + kk + c];
        }
        {
            int nn = t & 63, k0 = t >> 6;
            #pragma unroll
            for (int q = 0; q < 4; q++) {
                int f = kk + k0 + q * 4;
                Bs[(k0 + q * 4) * 64 + nn] = W1[((size_t)hh * 512 + f) * 64 + nn];
            }
        }
        __syncthreads();
        #pragma unroll
        for (int k = 0; k < 16; k++) {
            float4 a4 = *(const float4*)&As[k * 68 + tr * 4];
            ulonglong2 b2 = *(const ulonglong2*)&Bs[k * 64 + tc * 4];
            float av[4] = {a4.x, a4.y, a4.z, a4.w};
            #pragma unroll
            for (int i = 0; i < 4; i++) {
                unsigned au = __float_as_uint(av[i]);
                unsigned long long ad;
                asm("mov.b64 %0, {%1, %1};" : "=l"(ad) : "r"(au));
                asm("fma.rn.f32x2 %0, %1, %2, %0;" : "+l"(acc2[i][0]) : "l"(b2.x), "l"(ad));
                asm("fma.rn.f32x2 %0, %1, %2, %0;" : "+l"(acc2[i][1]) : "l"(b2.y), "l"(ad));
            }
        }
        __syncthreads();
    }
    #pragma unroll
    for (int i = 0; i < 4; i++) {
        float4 v;
        v.x = __uint_as_float((unsigned)(acc2[i][0] & 0xffffffffull));
        v.y = __uint_as_float((unsigned)(acc2[i][0] >> 32));
        v.z = __uint_as_float((unsigned)(acc2[i][1] & 0xffffffffull));
        v.w = __uint_as_float((unsigned)(acc2[i][1] >> 32));
        *(float4*)&g_Wh1[(size_t)(m0 + tr * 4 + i) * HD + n0 + tc * 4] = v;
    }
}

// ---------------- K2: merged logits + transpose-split ----------------
__global__ __launch_bounds__(256) void k_post(const float* __restrict__ a1p) {
    __shared__ float tile[32][33];
    int i0 = blockIdx.x * 32;
    int t = threadIdx.x, w = t >> 5, l = t & 31;
    {
        const float* a = &a1p[w * 128];
        float as0 = a[l], as1 = a[l + 32], ad0 = a[64 + l], ad1 = a[96 + l];
        for (int rr = 0; rr < 32; rr++) {
            const float* wh = &g_Wh1[(size_t)(i0 + rr) * HD + w * 64];
            float s = wh[l] * as0 + wh[l + 32] * as1;
            float d = wh[l] * ad0 + wh[l + 32] * ad1;
            #pragma unroll
            for (int o = 16; o; o >>= 1) {
                s += __shfl_xor_sync(0xffffffffu, s, o);
                d += __shfl_xor_sync(0xffffffffu, d, o);
            }
            if (l == 0) {
                int o = w * N + i0 + rr;
                g_ei[o]  = expf(s); g_eib[o] = expf(0.2f * s);
                g_edj[o] = expf(d); g_ebj[o] = expf(0.2f * d);
            }
        }
    }
    int tx = t & 31, ty = t >> 5;
    for (int cc = 0; cc < 16; cc++) {
        int c0 = cc * 32;
        __syncthreads();
        #pragma unroll
        for (int q = 0; q < 4; q++)
            tile[ty + q * 8][tx] = g_Wh1[(size_t)(i0 + ty + q * 8) * HD + c0 + tx];
        __syncthreads();
        float v[4];
        #pragma unroll
        for (int k = 0; k < 4; k++) v[k] = tile[ty * 4 + k][tx];
        unsigned h0, h1, l0, l1;
        asm("cvt.rn.bf16x2.f32 %0, %1, %2;" : "=r"(h0) : "f"(v[1]), "f"(v[0]));
        asm("cvt.rn.bf16x2.f32 %0, %1, %2;" : "=r"(h1) : "f"(v[3]), "f"(v[2]));
        float q0 = v[0] - __uint_as_float(h0 << 16);
        float q1 = v[1] - __uint_as_float(h0 & 0xffff0000u);
        float q2 = v[2] - __uint_as_float(h1 << 16);
        float q3 = v[3] - __uint_as_float(h1 & 0xffff0000u);
        asm("cvt.rn.bf16x2.f32 %0, %1, %2;" : "=r"(l0) : "f"(q1), "f"(q0));
        asm("cvt.rn.bf16x2.f32 %0, %1, %2;" : "=r"(l1) : "f"(q3), "f"(q2));
        size_t off = (size_t)(c0 + tx) * N + i0 + ty * 4;
        *(uint2*)&g_WT_hi[off] = make_uint2(h0, h1);
        *(uint2*)&g_WT_lo[off] = make_uint2(l0, l1);
    }
}

// ---------------- K3: layer-1 attention via mma.sync, pipelined (unchanged) ----------------
#define PSTR 40
__global__ __launch_bounds__(256, 2) void k_att1_mma(void) {
    __shared__ __align__(16) unsigned short sPh[128 * PSTR], sPl[128 * PSTR];
    __shared__ __align__(16) unsigned short sBh[2][64 * PSTR], sBl[2][64 * PSTR];
    __shared__ __align__(16) float sEd[32], sEb[32];
    __shared__ float zbuf[256];

    int t = threadIdx.x, lane = t & 31, w = t >> 5;
    int head = blockIdx.x & 7, i0 = (blockIdx.x >> 3) * 128;
    int r = t & 127, jh = t >> 7;
    int m0 = w * 16;

    float ei  = g_ei [head * N + i0 + r];
    float eib = g_eib[head * N + i0 + r];
    unsigned pBh = sm2u32(sPh), pBl = sm2u32(sPl);
    unsigned bBh = sm2u32(sBh), bBl = sm2u32(sBl);

    int rowA = m0 + (lane & 7) + ((lane >> 3) & 1) * 8;
    unsigned aoff = (unsigned)(rowA * PSTR + ((lane >> 4) & 1) * 8) * 2;
    unsigned boff = (unsigned)(((lane & 7) + ((lane >> 4) & 1) * 8) * PSTR
                               + ((lane >> 3) & 1) * 8) * 2;

    int sn = t >> 2, sp = t & 3;
    const uint4* gwh = (const uint4*)&g_WT_hi[(size_t)(head * 64 + sn) * N] + sp;
    const uint4* gwl = (const uint4*)&g_WT_lo[(size_t)(head * 64 + sn) * N] + sp;

    float acc[8][4];
    #pragma unroll
    for (int q = 0; q < 8; q++)
        #pragma unroll
        for (int k = 0; k < 4; k++) acc[q][k] = 0.f;
    float zl = 0.f;

    uint4 rbh = gwh[0], rbl = gwl[0];
    float rexp = (t < 32) ? g_edj[head * N + t]
               : (t < 64) ? g_ebj[head * N + (t - 32)] : 0.f;
    unsigned radj = g_adjT[(size_t)0 * N + i0 + r];

    for (int c = 0; c < 128; c++) {
        int buf = c & 1;
        *(uint4*)&sBh[buf][sn * PSTR + sp * 8] = rbh;
        *(uint4*)&sBl[buf][sn * PSTR + sp * 8] = rbl;
        if (t < 32) sEd[t] = rexp; else if (t < 64) sEb[t - 32] = rexp;
        unsigned bits = radj >> (jh * 16);
        if (c + 1 < 128) {
            rbh = gwh[(c + 1) * 4];
            rbl = gwl[(c + 1) * 4];
            if (t < 64)
                rexp = (t < 32) ? g_edj[head * N + (c + 1) * 32 + t]
                                : g_ebj[head * N + (c + 1) * 32 + (t - 32)];
            radj = g_adjT[(size_t)(c + 1) * N + i0 + r];
        }
        __syncthreads();
        {
            #pragma unroll
            for (int u = 0; u < 4; u++) {
                float4 e = ((const float4*)sEd)[jh * 4 + u];
                float4 b = ((const float4*)sEb)[jh * 4 + u];
                float p0 = fmaxf(ei * e.x, eib * b.x);
                float p1 = fmaxf(ei * e.y, eib * b.y);
                float p2 = fmaxf(ei * e.z, eib * b.z);
                float p3 = fmaxf(ei * e.w, eib * b.w);
                p0 = ((bits >> (u * 4 + 0)) & 1u) ? p0 : 0.f;
                p1 = ((bits >> (u * 4 + 1)) & 1u) ? p1 : 0.f;
                p2 = ((bits >> (u * 4 + 2)) & 1u) ? p2 : 0.f;
                p3 = ((bits >> (u * 4 + 3)) & 1u) ? p3 : 0.f;
                zl += (p0 + p1) + (p2 + p3);
                unsigned h0, h1, l0, l1;
                asm("cvt.rn.bf16x2.f32 %0, %1, %2;" : "=r"(h0) : "f"(p1), "f"(p0));
                asm("cvt.rn.bf16x2.f32 %0, %1, %2;" : "=r"(h1) : "f"(p3), "f"(p2));
                float q0 = p0 - __uint_as_float(h0 << 16);
                float q1 = p1 - __uint_as_float(h0 & 0xffff0000u);
                float q2 = p2 - __uint_as_float(h1 << 16);
                float q3 = p3 - __uint_as_float(h1 & 0xffff0000u);
                asm("cvt.rn.bf16x2.f32 %0, %1, %2;" : "=r"(l0) : "f"(q1), "f"(q0));
                asm("cvt.rn.bf16x2.f32 %0, %1, %2;" : "=r"(l1) : "f"(q3), "f"(q2));
                int o = r * PSTR + jh * 16 + u * 4;
                *(uint2*)&sPh[o] = make_uint2(h0, h1);
                *(uint2*)&sPl[o] = make_uint2(l0, l1);
            }
        }
        __syncthreads();
        unsigned bB = (unsigned)(buf * 64 * PSTR * 2);
        #pragma unroll
        for (int ks = 0; ks < 2; ks++) {
            unsigned Ah[4], Al[4];
            LDSM4(Ah, pBh + aoff + ks * 32);
            LDSM4(Al, pBl + aoff + ks * 32);
            #pragma unroll
            for (int gp = 0; gp < 2; gp++) {
                unsigned B0h[4], B0l[4], B1h[4], B1l[4];
                unsigned bo0 = boff + (gp * 2 + 0) * (16 * PSTR * 2) + ks * 32;
                unsigned bo1 = boff + (gp * 2 + 1) * (16 * PSTR * 2) + ks * 32;
                LDSM4(B0h, bBh + bB + bo0);
                LDSM4(B1h, bBh + bB + bo1);
                LDSM4(B0l, bBl + bB + bo0);
                LDSM4(B1l, bBl + bB + bo1);
                float *a0 = acc[gp * 4 + 0], *a1 = acc[gp * 4 + 1];
                float *a2 = acc[gp * 4 + 2], *a3 = acc[gp * 4 + 3];
                MMA(a0, Ah, B0h[0], B0h[1]); MMA(a1, Ah, B0h[2], B0h[3]);
                MMA(a2, Ah, B1h[0], B1h[1]); MMA(a3, Ah, B1h[2], B1h[3]);
                MMA(a0, Al, B0h[0], B0h[1]); MMA(a1, Al, B0h[2], B0h[3]);
                MMA(a2, Al, B1h[0], B1h[1]); MMA(a3, Al, B1h[2], B1h[3]);
                MMA(a0, Ah, B0l[0], B0l[1]); MMA(a1, Ah, B0l[2], B0l[3]);
                MMA(a2, Ah, B1l[0], B1l[1]); MMA(a3, Ah, B1l[2], B1l[3]);
            }
        }
        __syncthreads();
    }

    zbuf[t] = zl;
    __syncthreads();

    int rr0 = m0 + (lane >> 2), rr1 = rr0 + 8;
    float z0 = 1.f / (zbuf[rr0] + zbuf[rr0 + 128]);
    float z1 = 1.f / (zbuf[rr1] + zbuf[rr1 + 128]);
    float* d0 = &g_hcat[(size_t)(i0 + rr0) * HD + head * 64 + (lane & 3) * 2];
    float* d1 = &g_hcat[(size_t)(i0 + rr1) * HD + head * 64 + (lane & 3) * 2];
    #pragma unroll
    for (int nt = 0; nt < 8; nt++) {
        float v0 = acc[nt][0] * z0, v1 = acc[nt][1] * z0;
        float v2 = acc[nt][2] * z1, v3 = acc[nt][3] * z1;
        v0 = (v0 > 0.f) ? v0 : (expf(v0) - 1.f);
        v1 = (v1 > 0.f) ? v1 : (expf(v1) - 1.f);
        v2 = (v2 > 0.f) ? v2 : (expf(v2) - 1.f);
        v3 = (v3 > 0.f) ? v3 : (expf(v3) - 1.f);
        *(float2*)(d0 + nt * 8) = make_float2(v0, v1);
        *(float2*)(d1 + nt * 8) = make_float2(v2, v3);
    }
}

// ---------------- K4: Wh2 = hcat @ W2 + layer-2 logits + transpose-split ----------------
__global__ __launch_bounds__(256) void k_l2prep(const float* __restrict__ W2,
                                                const float* __restrict__ a2) {
    __shared__ float sH[16 * NFEAT];
    __shared__ float sWh[16 * NCLASS];
    int i0 = blockIdx.x * 16, t = threadIdx.x;
    for (int idx = t; idx < 16 * NFEAT; idx += 256)
        sH[idx] = g_hcat[(size_t)i0 * NFEAT + idx];
    __syncthreads();
    int r = t >> 4, c = t & 15;
    float acc = 0.f;
    #pragma unroll 4
    for (int f = 0; f < NFEAT; f++)
        acc += sH[r * NFEAT + f] * W2[f * NCLASS + c];
    sWh[r * NCLASS + c] = acc;
    __syncthreads();
    if (t < 16) {
        float fs = 0.f, fd = 0.f;
        #pragma unroll
        for (int c2 = 0; c2 < NCLASS; c2++) {
            float v = sWh[t * NCLASS + c2];
            fs += v * a2[c2];
            fd += v * a2[NCLASS + c2];
        }
        int i = i0 + t;
        g_ei2[i] = expf(fs);  g_eib2[i] = expf(0.2f * fs);
        g_ed2[i] = expf(fd);  g_ed2b[i] = expf(0.2f * fd);
    }
    // transpose split: thread t -> col c2 = t>>4, row rr = t&15
    {
        int c2 = t >> 4, rr = t & 15;
        float v = sWh[rr * NCLASS + c2];
        unsigned short hs, ls;
        asm("cvt.rn.bf16.f32 %0, %1;" : "=h"(hs) : "f"(v));
        float hf = __uint_as_float((unsigned)hs << 16);
        float lo = v - hf;
        asm("cvt.rn.bf16.f32 %0, %1;" : "=h"(ls) : "f"(lo));
        size_t off = (size_t)c2 * N + i0 + rr;
        g_WT2_hi[off] = hs;
        g_WT2_lo[off] = ls;
    }
}

// ---------------- K5: layer-2 attention via mma.sync (no ELU) ----------------
// CTA = 16 rows, 8 warps; warp w owns j-stripe w*32 within each 256-j chunk.
// Per-warp private P/B buffers -> no block barriers in the main loop.
// FIX vs R14: stage ALL 4 j-parts of the 16x32 B tile (each lane does 2 uint4
// per buffer: parts {l>>4, (l>>4)+2}); R14 staged only parts 0-1, leaving
// j 16..31 uninitialized -> NaN.
__global__ __launch_bounds__(256) void k_att2_mma(float* __restrict__ out) {
    __shared__ __align__(16) unsigned char sm[40960];   // [0,20480): P, [20480,40960): B
    __shared__ float sZr[8][16];
    int t = threadIdx.x, l = t & 31, w = t >> 5;
    int i0 = blockIdx.x * 16;
    int r = l & 15, jh2 = l >> 4;

    float ei  = g_ei2 [i0 + r];
    float eib = g_eib2[i0 + r];
    unsigned base = sm2u32(sm);
    unsigned ph = base + w * 2560, pl = ph + 1280;
    unsigned bh = base + 20480 + w * 2560, bl = bh + 1280;

    int rowA = (l & 7) + ((l >> 3) & 1) * 8;
    unsigned aoff = (unsigned)(rowA * PSTR + ((l >> 4) & 1) * 8) * 2;
    unsigned boff = (unsigned)(((l & 7) + ((l >> 4) & 1) * 8) * PSTR + ((l >> 3) & 1) * 8) * 2;

    int sn = l & 15, shalf = l >> 4;
    float acc[2][4] = {};
    float zl = 0.f;

    for (int c = 0; c < 16; c++) {
        int j0 = c * 256 + w * 32;
        // stage B (Wh2^T tile 16n x 32j, hi/lo): lane covers parts {shalf, shalf+2}
        #pragma unroll
        for (int pp = 0; pp < 2; pp++) {
            int part = shalf + pp * 2;
            *(uint4*)(sm + 20480 + w * 2560 + (sn * PSTR + part * 8) * 2) =
                *(const uint4*)&g_WT2_hi[(size_t)sn * N + j0 + part * 8];
            *(uint4*)(sm + 20480 + w * 2560 + 1280 + (sn * PSTR + part * 8) * 2) =
                *(const uint4*)&g_WT2_lo[(size_t)sn * N + j0 + part * 8];
        }
        // build masked P (16 j per lane)
        unsigned bits = g_adjT[(size_t)(c * 8 + w) * N + i0 + r] >> (jh2 * 16);
        #pragma unroll
        for (int u = 0; u < 4; u++) {
            float4 e = *(const float4*)&g_ed2 [j0 + jh2 * 16 + u * 4];
            float4 b = *(const float4*)&g_ed2b[j0 + jh2 * 16 + u * 4];
            float p0 = fmaxf(ei * e.x, eib * b.x);
            float p1 = fmaxf(ei * e.y, eib * b.y);
            float p2 = fmaxf(ei * e.z, eib * b.z);
            float p3 = fmaxf(ei * e.w, eib * b.w);
            p0 = ((bits >> (u * 4 + 0)) & 1u) ? p0 : 0.f;
            p1 = ((bits >> (u * 4 + 1)) & 1u) ? p1 : 0.f;
            p2 = ((bits >> (u * 4 + 2)) & 1u) ? p2 : 0.f;
            p3 = ((bits >> (u * 4 + 3)) & 1u) ? p3 : 0.f;
            zl += (p0 + p1) + (p2 + p3);
            unsigned h0, h1, l0, l1;
            asm("cvt.rn.bf16x2.f32 %0, %1, %2;" : "=r"(h0) : "f"(p1), "f"(p0));
            asm("cvt.rn.bf16x2.f32 %0, %1, %2;" : "=r"(h1) : "f"(p3), "f"(p2));
            float q0 = p0 - __uint_as_float(h0 << 16);
            float q1 = p1 - __uint_as_float(h0 & 0xffff0000u);
            float q2 = p2 - __uint_as_float(h1 << 16);
            float q3 = p3 - __uint_as_float(h1 & 0xffff0000u);
            asm("cvt.rn.bf16x2.f32 %0, %1, %2;" : "=r"(l0) : "f"(q1), "f"(q0));
            asm("cvt.rn.bf16x2.f32 %0, %1, %2;" : "=r"(l1) : "f"(q3), "f"(q2));
            unsigned o = (unsigned)(r * PSTR + jh2 * 16 + u * 4) * 2;
            *(uint2*)(sm + w * 2560 + o)        = make_uint2(h0, h1);
            *(uint2*)(sm + w * 2560 + 1280 + o) = make_uint2(l0, l1);
        }
        __syncwarp();
        #pragma unroll
        for (int ks = 0; ks < 2; ks++) {
            unsigned Ah[4], Al[4], Bh[4], Bl[4];
            LDSM4(Ah, ph + aoff + ks * 32);
            LDSM4(Al, pl + aoff + ks * 32);
            LDSM4(Bh, bh + boff + ks * 32);
            LDSM4(Bl, bl + boff + ks * 32);
            MMA(acc[0], Ah, Bh[0], Bh[1]); MMA(acc[1], Ah, Bh[2], Bh[3]);
            MMA(acc[0], Al, Bh[0], Bh[1]); MMA(acc[1], Al, Bh[2], Bh[3]);
            MMA(acc[0], Ah, Bl[0], Bl[1]); MMA(acc[1], Ah, Bl[2], Bl[3]);
        }
        __syncwarp();
    }

    zl += __shfl_xor_sync(0xffffffffu, zl, 16);
    if (l < 16) sZr[w][l] = zl;
    __syncthreads();                     // everyone done with P region
    float* sAcc = (float*)sm;            // reuse P region: 8 x 256 floats
    #pragma unroll
    for (int nt = 0; nt < 2; nt++) {
        int bc = nt * 8 + (l & 3) * 2, r0 = l >> 2;
        sAcc[w * 256 + r0 * 16 + bc]           = acc[nt][0];
        sAcc[w * 256 + r0 * 16 + bc + 1]       = acc[nt][1];
        sAcc[w * 256 + (r0 + 8) * 16 + bc]     = acc[nt][2];
        sAcc[w * 256 + (r0 + 8) * 16 + bc + 1] = acc[nt][3];
    }
    __syncthreads();
    {
        int rr = t >> 4, cc = t & 15;
        float s = 0.f, z = 0.f;
        #pragma unroll
        for (int w2 = 0; w2 < 8; w2++) {
            s += sAcc[w2 * 256 + rr * 16 + cc];
            z += sZr[w2][rr];
        }
        out[(size_t)(i0 + rr) * NCLASS + cc] = s / z;
    }
}

// ---------------- launcher ----------------
extern "C" void kernel_launch(void* const* d_in, const int* in_sizes, int n_in,
                              void* d_out, int out_size) {
    const float* x   = (const float*)d_in[0];
    const int*   adj = (const int*)  d_in[1];
    const float* W1  = (const float*)d_in[2];
    const float* a1  = (const float*)d_in[3];
    const float* W2  = (const float*)d_in[4];
    const float* a2  = (const float*)d_in[5];
    float* out = (float*)d_out;

    k_pack<<<N, 1024>>>(adj);                       // 0
    k_gemm1<<<dim3(N / 64, HD / 64), 256>>>(x, W1); // 1
    k_post<<<N / 32, 256>>>(a1);                    // 2
    k_att1_mma<<<256, 256>>>();                     // 3  <- profiled slot
    k_l2prep<<<N / 16, 256>>>(W2, a2);              // 4
    k_att2_mma<<<N / 16, 256>>>(out);               // 5
}